// round 12
// baseline (speedup 1.0000x reference)
#include <cuda_runtime.h>
#include <math.h>
#include <stdint.h>

// Problem shape (fixed by setup_inputs)
constexpr int Bc = 8;     // batch
constexpr int Nc = 2048;  // nodes
constexpr int Fc = 128;   // in features
constexpr int Oc = 128;   // out features

// Scratch (static __device__ — allocation-free per harness rules)
__device__ float g_d[Bc * Nc];            // 1/(eps+sqrt(rowsum(A_hat)))
__device__ float g_z[Bc * Nc * Oc];       // z[m,o]  = d[m] * (x W)[m,o]   (row-major)
__device__ float g_zT[Bc * Oc * Nc];      // zT[o,m] = same, transposed (n-major B operand)

// ---------------------------------------------------------------------------
// Generic-PTX helpers (sm_80+ features only: cp.async, ldmatrix, mma.sync tf32)
// ---------------------------------------------------------------------------
__device__ __forceinline__ uint32_t smem_u32(const void* p) {
    uint32_t a;
    asm("{ .reg .u64 t; cvta.to.shared.u64 t, %1; cvt.u32.u64 %0, t; }"
        : "=r"(a) : "l"(p));
    return a;
}
__device__ __forceinline__ void cp16(uint32_t s, const void* g) {
    asm volatile("cp.async.cg.shared.global [%0], [%1], 16;\n" :: "r"(s), "l"(g));
}
#define CP_COMMIT()  asm volatile("cp.async.commit_group;\n" ::: "memory")
#define CP_WAIT(N)   asm volatile("cp.async.wait_group " #N ";\n" ::: "memory")

// ldmatrix x4 over four 8-row x 16B sub-tiles (raw 32-bit payload is fine)
#define LDSM4(r, addr) \
    asm volatile("ldmatrix.sync.aligned.m8n8.x4.shared.b16 {%0,%1,%2,%3}, [%4];" \
                 : "=r"((r)[0]), "=r"((r)[1]), "=r"((r)[2]), "=r"((r)[3]) \
                 : "r"(addr))

// round-to-nearest tf32 (halves truncation error vs raw HMMA truncate)
#define TO_TF32(x) asm volatile("cvt.rna.tf32.f32 %0, %0;" : "+r"(x))

#define MMA_TF32(c, a, bb) \
    asm volatile( \
        "mma.sync.aligned.m16n8k8.row.col.f32.tf32.tf32.f32 " \
        "{%0,%1,%2,%3}, {%4,%5,%6,%7}, {%8,%9}, {%0,%1,%2,%3};" \
        : "+f"((c)[0]), "+f"((c)[1]), "+f"((c)[2]), "+f"((c)[3]) \
        : "r"((a)[0]), "r"((a)[1]), "r"((a)[2]), "r"((a)[3]), \
          "r"((bb)[0]), "r"((bb)[1]))

// ---------------------------------------------------------------------------
// Kernel 1: row sums of A_hat -> d.  One warp per row. (HBM-bound, 74% DRAM)
// ---------------------------------------------------------------------------
__global__ __launch_bounds__(256) void k_rowsum(const float* __restrict__ adj) {
    int warps_per_block = blockDim.x >> 5;
    int row = blockIdx.x * warps_per_block + (threadIdx.x >> 5);
    if (row >= Bc * Nc) return;
    int lane = threadIdx.x & 31;
    const float4* a = reinterpret_cast<const float4*>(adj + (size_t)row * Nc);
    float s = 0.f;
#pragma unroll 4
    for (int i = lane; i < Nc / 4; i += 32) {
        float4 v = __ldg(a + i);
        s += (v.x + v.y) + (v.z + v.w);
    }
#pragma unroll
    for (int off = 16; off; off >>= 1) s += __shfl_xor_sync(0xffffffffu, s, off);
    if (lane == 0) {
        int n = row & (Nc - 1);
        float diag = __ldg(adj + (size_t)row * Nc + n);
        float rs = s - diag + 1.0f;
        g_d[row] = 1.0f / (1e-6f + sqrtf(rs));
    }
}

// ---------------------------------------------------------------------------
// Kernel 2: z[r,o] = d[r] * sum_f x[r,f] W[f,o]; writes row-major AND transposed.
// Exact fp32 so tf32 error enters only once (in k_main).
// ---------------------------------------------------------------------------
__global__ __launch_bounds__(256) void k_xw(const float* __restrict__ x,
                                            const float* __restrict__ W) {
    __shared__ float As[8][132];
    __shared__ float Bs[8][128];
    int tid = threadIdx.x;
    int tx = tid & 15, ty = tid >> 4;
    int rowBase = blockIdx.x * 128;

    float c[8][8] = {};

    int aIdx = tid * 4;
    int aR = aIdx >> 3, aK = aIdx & 7;
    int bK = tid >> 5, bC = (tid & 31) * 4;

    for (int k0 = 0; k0 < Fc; k0 += 8) {
        float4 va = *reinterpret_cast<const float4*>(
            x + (size_t)(rowBase + aR) * Fc + k0 + aK);
        float4 vb = *reinterpret_cast<const float4*>(
            W + (size_t)(bK + k0) * Oc + bC);
        __syncthreads();
        As[aK + 0][aR] = va.x; As[aK + 1][aR] = va.y;
        As[aK + 2][aR] = va.z; As[aK + 3][aR] = va.w;
        *reinterpret_cast<float4*>(&Bs[bK][bC]) = vb;
        __syncthreads();
#pragma unroll
        for (int k = 0; k < 8; ++k) {
            float a[8], b[8];
#pragma unroll
            for (int i = 0; i < 8; i++) a[i] = As[k][ty * 8 + i];
#pragma unroll
            for (int j = 0; j < 8; j++) b[j] = Bs[k][tx * 8 + j];
#pragma unroll
            for (int i = 0; i < 8; i++)
#pragma unroll
                for (int j = 0; j < 8; j++) c[i][j] += a[i] * b[j];
        }
    }

    float dvv[8];
#pragma unroll
    for (int i = 0; i < 8; i++) dvv[i] = g_d[rowBase + ty * 8 + i];

    // row-major z
#pragma unroll
    for (int i = 0; i < 8; i++) {
        int row = rowBase + ty * 8 + i;
#pragma unroll
        for (int j = 0; j < 8; j += 4) {
            float4 v;
            v.x = dvv[i] * c[i][j + 0];
            v.y = dvv[i] * c[i][j + 1];
            v.z = dvv[i] * c[i][j + 2];
            v.w = dvv[i] * c[i][j + 3];
            *reinterpret_cast<float4*>(g_z + (size_t)row * Oc + tx * 8 + j) = v;
        }
    }
    // transposed zT[b][o][m]
    int bb = rowBase >> 11;
    int mbase = (rowBase & (Nc - 1)) + ty * 8;
#pragma unroll
    for (int j = 0; j < 8; j++) {
        int o = tx * 8 + j;
        float* dst = g_zT + ((size_t)bb * Oc + o) * Nc + mbase;
        float4 v0, v1;
        v0.x = dvv[0] * c[0][j]; v0.y = dvv[1] * c[1][j];
        v0.z = dvv[2] * c[2][j]; v0.w = dvv[3] * c[3][j];
        v1.x = dvv[4] * c[4][j]; v1.y = dvv[5] * c[5][j];
        v1.z = dvv[6] * c[6][j]; v1.w = dvv[7] * c[7][j];
        *reinterpret_cast<float4*>(dst)     = v0;
        *reinterpret_cast<float4*>(dst + 4) = v1;
    }
}

// ---------------------------------------------------------------------------
// Kernel 3: tf32 mma.sync GEMM (generic PTX — compiles for compute_103).
// out[b,n,o] = relu( d[n] * ( sum_m A[b,n,m] z[b,m,o] + (1-A[b,n,n]) z[b,n,o] ) )
// BM=128, BN=128, BK=32, 4-stage cp.async pipeline (128 KB smem).
// 8 warps: warpM = wid&1 (2 x 64 rows), warpN = wid>>1 (4 x 32 cols).
// Per warp: 4x4 grid of m16n8k8 tiles. Fragments via ldmatrix from
// XOR-swizzled K-major tiles (A = adj rows; B = zT rows, both k-contiguous).
// ---------------------------------------------------------------------------
constexpr int BK      = 32;
constexpr int K_ITERS = Nc / BK;              // 64
constexpr int TILE_B  = 128 * BK * 4;         // 16384 per operand
constexpr int STAGE_B = 2 * TILE_B;           // 32768 (A + B)
constexpr int SMEM_SZ = 4 * STAGE_B;          // 131072

// swizzled 16B-chunk offset within a [128 rows x 32 floats] tile
__device__ __forceinline__ uint32_t sw(int r, int ch) {   // ch in 0..7 (16B units)
    return (uint32_t)(r * 128) + (uint32_t)(((ch ^ (r & 7)) << 4));
}
// ldmatrix.x4 source address for lane: 4 sub-tiles (rows +0/+8, chunks +0/+1)
__device__ __forceinline__ uint32_t ldsm_addr(uint32_t base, int rowBase,
                                              int chunkBase, int lane) {
    int row = rowBase + (lane & 7) + (((lane >> 3) & 1) << 3);
    int ch  = chunkBase + (lane >> 4);
    return base + sw(row, ch);
}

__global__ __launch_bounds__(256, 1) void k_main_mma(const float* __restrict__ adj,
                                                     float* __restrict__ out) {
    extern __shared__ __align__(1024) char smem[];
    uint32_t sb = smem_u32(smem);
    int tid = threadIdx.x, wid = tid >> 5, lane = tid & 31;
    int b = blockIdx.y, rowBase = blockIdx.x * 128;
    int warpM = wid & 1, warpN = wid >> 1;

    const float* A  = adj  + (size_t)b * Nc * Nc;
    const float* ZT = g_zT + (size_t)b * Oc * Nc;

    float c[4][4][4] = {};

    auto issue = [&](int it) {
        int s = it & 3;
        uint32_t baseA = sb + s * STAGE_B;
        uint32_t baseB = baseA + TILE_B;
        int k0 = it * BK;
#pragma unroll
        for (int t = 0; t < 4; t++) {          // 1024 chunks per operand / 256 thr
            int idx = tid + t * 256;
            int r = idx >> 3, ch = idx & 7;
            uint32_t so = sw(r, ch);
            cp16(baseA + so, A  + (size_t)(rowBase + r) * Nc + k0 + ch * 4);
            cp16(baseB + so, ZT + (size_t)r * Nc + k0 + ch * 4);
        }
        CP_COMMIT();
    };

    issue(0); issue(1); issue(2);

    for (int it = 0; it < K_ITERS; ++it) {
        if (it + 3 < K_ITERS) { issue(it + 3); CP_WAIT(3); }
        else                  { CP_WAIT(0); }
        __syncthreads();

        int s = it & 3;
        uint32_t baseA = sb + s * STAGE_B;
        uint32_t baseB = baseA + TILE_B;
#pragma unroll
        for (int ks = 0; ks < 4; ++ks) {       // four k8 steps within BK=32
            uint32_t a[4][4];
#pragma unroll
            for (int mt = 0; mt < 4; ++mt) {
                uint32_t ad = ldsm_addr(baseA, warpM * 64 + mt * 16, ks * 2, lane);
                LDSM4(a[mt], ad);
#pragma unroll
                for (int q = 0; q < 4; q++) TO_TF32(a[mt][q]);
            }
            uint32_t bf[4][2];
#pragma unroll
            for (int p = 0; p < 2; ++p) {      // two n16 groups -> four n8 tiles
                uint32_t r4[4];
                uint32_t ad = ldsm_addr(baseB, warpN * 32 + p * 16, ks * 2, lane);
                LDSM4(r4, ad);
#pragma unroll
                for (int q = 0; q < 4; q++) TO_TF32(r4[q]);
                bf[2 * p + 0][0] = r4[0]; bf[2 * p + 0][1] = r4[2];
                bf[2 * p + 1][0] = r4[1]; bf[2 * p + 1][1] = r4[3];
            }
#pragma unroll
            for (int mt = 0; mt < 4; ++mt)
#pragma unroll
                for (int nt = 0; nt < 4; ++nt)
                    MMA_TF32(c[mt][nt], a[mt], bf[nt]);
        }
        __syncthreads();
    }

    // Epilogue: diagonal correction + d[n] scale + relu, from C fragments.
    // c0,c1 -> (row = lane/4, cols 2*(lane%4)+{0,1}); c2,c3 -> row+8.
    int gr = lane >> 2, tg = lane & 3;
#pragma unroll
    for (int mt = 0; mt < 4; ++mt) {
        int n0 = rowBase + warpM * 64 + mt * 16 + gr;
        int n1 = n0 + 8;
        size_t rg0 = (size_t)b * Nc + n0;
        size_t rg1 = (size_t)b * Nc + n1;
        float corr0 = 1.0f - __ldg(A + (size_t)n0 * Nc + n0);
        float corr1 = 1.0f - __ldg(A + (size_t)n1 * Nc + n1);
        float dv0 = g_d[rg0], dv1 = g_d[rg1];
#pragma unroll
        for (int nt = 0; nt < 4; ++nt) {
            int o = warpN * 32 + nt * 8 + 2 * tg;
            float2 z0 = *reinterpret_cast<const float2*>(g_z + rg0 * Oc + o);
            float2 z1 = *reinterpret_cast<const float2*>(g_z + rg1 * Oc + o);
            float2 v0, v1;
            v0.x = fmaxf(dv0 * (c[mt][nt][0] + corr0 * z0.x), 0.f);
            v0.y = fmaxf(dv0 * (c[mt][nt][1] + corr0 * z0.y), 0.f);
            v1.x = fmaxf(dv1 * (c[mt][nt][2] + corr1 * z1.x), 0.f);
            v1.y = fmaxf(dv1 * (c[mt][nt][3] + corr1 * z1.y), 0.f);
            *reinterpret_cast<float2*>(out + rg0 * Oc + o) = v0;
            *reinterpret_cast<float2*>(out + rg1 * Oc + o) = v1;
        }
    }
}

// ---------------------------------------------------------------------------
extern "C" void kernel_launch(void* const* d_in, const int* in_sizes, int n_in,
                              void* d_out, int out_size) {
    const float* x   = (const float*)d_in[0];   // [8,2048,128]
    const float* adj = (const float*)d_in[1];   // [8,2048,2048]
    const float* W   = (const float*)d_in[2];   // [128,128]
    float* out = (float*)d_out;                 // [8,2048,128]

    cudaFuncSetAttribute(k_main_mma, cudaFuncAttributeMaxDynamicSharedMemorySize,
                         SMEM_SZ);

    k_rowsum<<<(Bc * Nc) / 8, 256>>>(adj);
    k_xw<<<(Bc * Nc) / 128, 256>>>(x, W);
    k_main_mma<<<dim3(Nc / 128, Bc), 256, SMEM_SZ>>>(adj, out);
}

// round 13
// speedup vs baseline: 1.0039x; 1.0039x over previous
#include <cuda_runtime.h>
#include <math.h>
#include <stdint.h>

// Problem shape (fixed by setup_inputs)
constexpr int Bc = 8;     // batch
constexpr int Nc = 2048;  // nodes
constexpr int Fc = 128;   // in features
constexpr int Oc = 128;   // out features

// Scratch (static __device__ — allocation-free per harness rules)
__device__ float g_d[Bc * Nc];            // 1/(eps+sqrt(rowsum(A_hat)))
__device__ float g_z[Bc * Nc * Oc];       // z[m,o]  = d[m] * (x W)[m,o]   (row-major)
__device__ float g_zT[Bc * Oc * Nc];      // zT[o,m] = same, transposed (n-major B operand)

// ---------------------------------------------------------------------------
// Generic-PTX helpers (sm_80+ features only: cp.async, ldmatrix, mma.sync tf32)
// ---------------------------------------------------------------------------
__device__ __forceinline__ uint32_t smem_u32(const void* p) {
    uint32_t a;
    asm("{ .reg .u64 t; cvta.to.shared.u64 t, %1; cvt.u32.u64 %0, t; }"
        : "=r"(a) : "l"(p));
    return a;
}
__device__ __forceinline__ void cp16(uint32_t s, const void* g) {
    asm volatile("cp.async.cg.shared.global [%0], [%1], 16;\n" :: "r"(s), "l"(g));
}
#define CP_COMMIT()  asm volatile("cp.async.commit_group;\n" ::: "memory")
#define CP_WAIT(N)   asm volatile("cp.async.wait_group " #N ";\n" ::: "memory")

// ldmatrix x4 over four 8-row x 16B sub-tiles (raw 32-bit payload is fine)
#define LDSM4(r, addr) \
    asm volatile("ldmatrix.sync.aligned.m8n8.x4.shared.b16 {%0,%1,%2,%3}, [%4];" \
                 : "=r"((r)[0]), "=r"((r)[1]), "=r"((r)[2]), "=r"((r)[3]) \
                 : "r"(addr))

// round-to-nearest tf32 (halves truncation error vs raw HMMA truncate)
#define TO_TF32(x) asm volatile("cvt.rna.tf32.f32 %0, %0;" : "+r"(x))

#define MMA_TF32(c, a, bb) \
    asm volatile( \
        "mma.sync.aligned.m16n8k8.row.col.f32.tf32.tf32.f32 " \
        "{%0,%1,%2,%3}, {%4,%5,%6,%7}, {%8,%9}, {%0,%1,%2,%3};" \
        : "+f"((c)[0]), "+f"((c)[1]), "+f"((c)[2]), "+f"((c)[3]) \
        : "r"((a)[0]), "r"((a)[1]), "r"((a)[2]), "r"((a)[3]), \
          "r"((bb)[0]), "r"((bb)[1]))

// ---------------------------------------------------------------------------
// Kernel 1: row sums of A_hat -> d.  One warp per row. (HBM-bound, 74% DRAM)
// ---------------------------------------------------------------------------
__global__ __launch_bounds__(256) void k_rowsum(const float* __restrict__ adj) {
    int warps_per_block = blockDim.x >> 5;
    int row = blockIdx.x * warps_per_block + (threadIdx.x >> 5);
    if (row >= Bc * Nc) return;
    int lane = threadIdx.x & 31;
    const float4* a = reinterpret_cast<const float4*>(adj + (size_t)row * Nc);
    float s = 0.f;
#pragma unroll 4
    for (int i = lane; i < Nc / 4; i += 32) {
        float4 v = __ldg(a + i);
        s += (v.x + v.y) + (v.z + v.w);
    }
#pragma unroll
    for (int off = 16; off; off >>= 1) s += __shfl_xor_sync(0xffffffffu, s, off);
    if (lane == 0) {
        int n = row & (Nc - 1);
        float diag = __ldg(adj + (size_t)row * Nc + n);
        float rs = s - diag + 1.0f;
        g_d[row] = 1.0f / (1e-6f + sqrtf(rs));
    }
}

// ---------------------------------------------------------------------------
// Kernel 2: z[r,o] = d[r] * sum_f x[r,f] W[f,o]; writes row-major AND transposed.
// Exact fp32 so tf32 error enters only once (in k_main).
// ---------------------------------------------------------------------------
__global__ __launch_bounds__(256) void k_xw(const float* __restrict__ x,
                                            const float* __restrict__ W) {
    __shared__ float As[8][132];
    __shared__ float Bs[8][128];
    int tid = threadIdx.x;
    int tx = tid & 15, ty = tid >> 4;
    int rowBase = blockIdx.x * 128;

    float c[8][8] = {};

    int aIdx = tid * 4;
    int aR = aIdx >> 3, aK = aIdx & 7;
    int bK = tid >> 5, bC = (tid & 31) * 4;

    for (int k0 = 0; k0 < Fc; k0 += 8) {
        float4 va = *reinterpret_cast<const float4*>(
            x + (size_t)(rowBase + aR) * Fc + k0 + aK);
        float4 vb = *reinterpret_cast<const float4*>(
            W + (size_t)(bK + k0) * Oc + bC);
        __syncthreads();
        As[aK + 0][aR] = va.x; As[aK + 1][aR] = va.y;
        As[aK + 2][aR] = va.z; As[aK + 3][aR] = va.w;
        *reinterpret_cast<float4*>(&Bs[bK][bC]) = vb;
        __syncthreads();
#pragma unroll
        for (int k = 0; k < 8; ++k) {
            float a[8], b[8];
#pragma unroll
            for (int i = 0; i < 8; i++) a[i] = As[k][ty * 8 + i];
#pragma unroll
            for (int j = 0; j < 8; j++) b[j] = Bs[k][tx * 8 + j];
#pragma unroll
            for (int i = 0; i < 8; i++)
#pragma unroll
                for (int j = 0; j < 8; j++) c[i][j] += a[i] * b[j];
        }
    }

    float dvv[8];
#pragma unroll
    for (int i = 0; i < 8; i++) dvv[i] = g_d[rowBase + ty * 8 + i];

    // row-major z
#pragma unroll
    for (int i = 0; i < 8; i++) {
        int row = rowBase + ty * 8 + i;
#pragma unroll
        for (int j = 0; j < 8; j += 4) {
            float4 v;
            v.x = dvv[i] * c[i][j + 0];
            v.y = dvv[i] * c[i][j + 1];
            v.z = dvv[i] * c[i][j + 2];
            v.w = dvv[i] * c[i][j + 3];
            *reinterpret_cast<float4*>(g_z + (size_t)row * Oc + tx * 8 + j) = v;
        }
    }
    // transposed zT[b][o][m]
    int bb = rowBase >> 11;
    int mbase = (rowBase & (Nc - 1)) + ty * 8;
#pragma unroll
    for (int j = 0; j < 8; j++) {
        int o = tx * 8 + j;
        float* dst = g_zT + ((size_t)bb * Oc + o) * Nc + mbase;
        float4 v0, v1;
        v0.x = dvv[0] * c[0][j]; v0.y = dvv[1] * c[1][j];
        v0.z = dvv[2] * c[2][j]; v0.w = dvv[3] * c[3][j];
        v1.x = dvv[4] * c[4][j]; v1.y = dvv[5] * c[5][j];
        v1.z = dvv[6] * c[6][j]; v1.w = dvv[7] * c[7][j];
        *reinterpret_cast<float4*>(dst)     = v0;
        *reinterpret_cast<float4*>(dst + 4) = v1;
    }
}

// ---------------------------------------------------------------------------
// Kernel 3: tf32 mma.sync GEMM (generic PTX — compiles for compute_103).
// out[b,n,o] = relu( d[n] * ( sum_m A[b,n,m] z[b,m,o] + (1-A[b,n,n]) z[b,n,o] ) )
// BM=128, BN=128, BK=32, 4-stage cp.async pipeline (128 KB smem).
// 8 warps: warpM = wid&1 (2 x 64 rows), warpN = wid>>1 (4 x 32 cols).
// Per warp: 4x4 grid of m16n8k8 tiles. Fragments via ldmatrix from
// XOR-swizzled K-major tiles (A = adj rows; B = zT rows, both k-contiguous).
// ---------------------------------------------------------------------------
constexpr int BK      = 32;
constexpr int K_ITERS = Nc / BK;              // 64
constexpr int TILE_B  = 128 * BK * 4;         // 16384 per operand
constexpr int STAGE_B = 2 * TILE_B;           // 32768 (A + B)
constexpr int SMEM_SZ = 4 * STAGE_B;          // 131072

// swizzled 16B-chunk offset within a [128 rows x 32 floats] tile
__device__ __forceinline__ uint32_t sw(int r, int ch) {   // ch in 0..7 (16B units)
    return (uint32_t)(r * 128) + (uint32_t)(((ch ^ (r & 7)) << 4));
}
// ldmatrix.x4 source address for lane: 4 sub-tiles (rows +0/+8, chunks +0/+1)
__device__ __forceinline__ uint32_t ldsm_addr(uint32_t base, int rowBase,
                                              int chunkBase, int lane) {
    int row = rowBase + (lane & 7) + (((lane >> 3) & 1) << 3);
    int ch  = chunkBase + (lane >> 4);
    return base + sw(row, ch);
}

__global__ __launch_bounds__(256, 1) void k_main_mma(const float* __restrict__ adj,
                                                     float* __restrict__ out) {
    extern __shared__ __align__(1024) char smem[];
    uint32_t sb = smem_u32(smem);
    int tid = threadIdx.x, wid = tid >> 5, lane = tid & 31;
    int b = blockIdx.y, rowBase = blockIdx.x * 128;
    int warpM = wid & 1, warpN = wid >> 1;

    const float* A  = adj  + (size_t)b * Nc * Nc;
    const float* ZT = g_zT + (size_t)b * Oc * Nc;

    float c[4][4][4] = {};

    auto issue = [&](int it) {
        int s = it & 3;
        uint32_t baseA = sb + s * STAGE_B;
        uint32_t baseB = baseA + TILE_B;
        int k0 = it * BK;
#pragma unroll
        for (int t = 0; t < 4; t++) {          // 1024 chunks per operand / 256 thr
            int idx = tid + t * 256;
            int r = idx >> 3, ch = idx & 7;
            uint32_t so = sw(r, ch);
            cp16(baseA + so, A  + (size_t)(rowBase + r) * Nc + k0 + ch * 4);
            cp16(baseB + so, ZT + (size_t)r * Nc + k0 + ch * 4);
        }
        CP_COMMIT();
    };

    issue(0); issue(1); issue(2);

    for (int it = 0; it < K_ITERS; ++it) {
        if (it + 3 < K_ITERS) { issue(it + 3); CP_WAIT(3); }
        else                  { CP_WAIT(0); }
        __syncthreads();

        int s = it & 3;
        uint32_t baseA = sb + s * STAGE_B;
        uint32_t baseB = baseA + TILE_B;
#pragma unroll
        for (int ks = 0; ks < 4; ++ks) {       // four k8 steps within BK=32
            uint32_t a[4][4];
#pragma unroll
            for (int mt = 0; mt < 4; ++mt) {
                uint32_t ad = ldsm_addr(baseA, warpM * 64 + mt * 16, ks * 2, lane);
                LDSM4(a[mt], ad);
#pragma unroll
                for (int q = 0; q < 4; q++) TO_TF32(a[mt][q]);
            }
            uint32_t bf[4][2];
#pragma unroll
            for (int p = 0; p < 2; ++p) {      // two n16 groups -> four n8 tiles
                uint32_t r4[4];
                uint32_t ad = ldsm_addr(baseB, warpN * 32 + p * 16, ks * 2, lane);
                LDSM4(r4, ad);
#pragma unroll
                for (int q = 0; q < 4; q++) TO_TF32(r4[q]);
                bf[2 * p + 0][0] = r4[0]; bf[2 * p + 0][1] = r4[2];
                bf[2 * p + 1][0] = r4[1]; bf[2 * p + 1][1] = r4[3];
            }
#pragma unroll
            for (int mt = 0; mt < 4; ++mt)
#pragma unroll
                for (int nt = 0; nt < 4; ++nt)
                    MMA_TF32(c[mt][nt], a[mt], bf[nt]);
        }
        __syncthreads();
    }

    // Epilogue: diagonal correction + d[n] scale + relu, from C fragments.
    // c0,c1 -> (row = lane/4, cols 2*(lane%4)+{0,1}); c2,c3 -> row+8.
    int gr = lane >> 2, tg = lane & 3;
#pragma unroll
    for (int mt = 0; mt < 4; ++mt) {
        int n0 = rowBase + warpM * 64 + mt * 16 + gr;
        int n1 = n0 + 8;
        size_t rg0 = (size_t)b * Nc + n0;
        size_t rg1 = (size_t)b * Nc + n1;
        float corr0 = 1.0f - __ldg(A + (size_t)n0 * Nc + n0);
        float corr1 = 1.0f - __ldg(A + (size_t)n1 * Nc + n1);
        float dv0 = g_d[rg0], dv1 = g_d[rg1];
#pragma unroll
        for (int nt = 0; nt < 4; ++nt) {
            int o = warpN * 32 + nt * 8 + 2 * tg;
            float2 z0 = *reinterpret_cast<const float2*>(g_z + rg0 * Oc + o);
            float2 z1 = *reinterpret_cast<const float2*>(g_z + rg1 * Oc + o);
            float2 v0, v1;
            v0.x = fmaxf(dv0 * (c[mt][nt][0] + corr0 * z0.x), 0.f);
            v0.y = fmaxf(dv0 * (c[mt][nt][1] + corr0 * z0.y), 0.f);
            v1.x = fmaxf(dv1 * (c[mt][nt][2] + corr1 * z1.x), 0.f);
            v1.y = fmaxf(dv1 * (c[mt][nt][3] + corr1 * z1.y), 0.f);
            *reinterpret_cast<float2*>(out + rg0 * Oc + o) = v0;
            *reinterpret_cast<float2*>(out + rg1 * Oc + o) = v1;
        }
    }
}

// ---------------------------------------------------------------------------
extern "C" void kernel_launch(void* const* d_in, const int* in_sizes, int n_in,
                              void* d_out, int out_size) {
    const float* x   = (const float*)d_in[0];   // [8,2048,128]
    const float* adj = (const float*)d_in[1];   // [8,2048,2048]
    const float* W   = (const float*)d_in[2];   // [128,128]
    float* out = (float*)d_out;                 // [8,2048,128]

    cudaFuncSetAttribute(k_main_mma, cudaFuncAttributeMaxDynamicSharedMemorySize,
                         SMEM_SZ);

    k_rowsum<<<(Bc * Nc) / 8, 256>>>(adj);
    k_xw<<<(Bc * Nc) / 128, 256>>>(x, W);
    k_main_mma<<<dim3(Nc / 128, Bc), 256, SMEM_SZ>>>(adj, out);
}

// round 14
// speedup vs baseline: 1.0578x; 1.0537x over previous
#include <cuda_runtime.h>
#include <math.h>
#include <stdint.h>

// Problem shape (fixed by setup_inputs)
constexpr int Bc = 8;     // batch
constexpr int Nc = 2048;  // nodes
constexpr int Fc = 128;   // in features
constexpr int Oc = 128;   // out features

// Scratch (static __device__ — allocation-free per harness rules)
__device__ float g_d[Bc * Nc];            // 1/(eps+sqrt(rowsum(A_hat)))
__device__ float g_z[Bc * Nc * Oc];       // z[m,o] = d[m]*(xW)[m,o] exact fp32 (epilogue)
__device__ float g_zT[Bc * Oc * Nc];      // zT[o,m] = same, PRE-ROUNDED to tf32 (MMA B)

// ---------------------------------------------------------------------------
// Generic-PTX helpers (sm_80+ features only: cp.async, ldmatrix, mma.sync tf32)
// ---------------------------------------------------------------------------
__device__ __forceinline__ uint32_t smem_u32(const void* p) {
    uint32_t a;
    asm("{ .reg .u64 t; cvta.to.shared.u64 t, %1; cvt.u32.u64 %0, t; }"
        : "=r"(a) : "l"(p));
    return a;
}
__device__ __forceinline__ void cp16(uint32_t s, const void* g) {
    asm volatile("cp.async.cg.shared.global [%0], [%1], 16;\n" :: "r"(s), "l"(g));
}
#define CP_COMMIT()  asm volatile("cp.async.commit_group;\n" ::: "memory")
#define CP_WAIT(N)   asm volatile("cp.async.wait_group " #N ";\n" ::: "memory")

#define LDSM4(r, addr) \
    asm volatile("ldmatrix.sync.aligned.m8n8.x4.shared.b16 {%0,%1,%2,%3}, [%4];" \
                 : "=r"((r)[0]), "=r"((r)[1]), "=r"((r)[2]), "=r"((r)[3]) \
                 : "r"(addr))

#define TO_TF32(x) asm volatile("cvt.rna.tf32.f32 %0, %0;" : "+r"(x))

#define MMA_TF32(c, a, bb) \
    asm volatile( \
        "mma.sync.aligned.m16n8k8.row.col.f32.tf32.tf32.f32 " \
        "{%0,%1,%2,%3}, {%4,%5,%6,%7}, {%8,%9}, {%0,%1,%2,%3};" \
        : "+f"((c)[0]), "+f"((c)[1]), "+f"((c)[2]), "+f"((c)[3]) \
        : "r"((a)[0]), "r"((a)[1]), "r"((a)[2]), "r"((a)[3]), \
          "r"((bb)[0]), "r"((bb)[1]))

// ---------------------------------------------------------------------------
// Kernel 1: row sums of A_hat -> d.  One warp per row, deeper MLP.
// ---------------------------------------------------------------------------
__global__ __launch_bounds__(256) void k_rowsum(const float* __restrict__ adj) {
    int row = blockIdx.x * 8 + (threadIdx.x >> 5);
    if (row >= Bc * Nc) return;
    int lane = threadIdx.x & 31;
    const float4* a = reinterpret_cast<const float4*>(adj + (size_t)row * Nc);
    float s0 = 0.f, s1 = 0.f;
    // 512 float4 per row / 32 lanes = 16 iters; unroll fully in pairs -> MLP 16
#pragma unroll 8
    for (int i = lane; i < Nc / 4; i += 64) {
        float4 v0 = __ldg(a + i);
        float4 v1 = __ldg(a + i + 32);
        s0 += (v0.x + v0.y) + (v0.z + v0.w);
        s1 += (v1.x + v1.y) + (v1.z + v1.w);
    }
    float s = s0 + s1;
#pragma unroll
    for (int off = 16; off; off >>= 1) s += __shfl_xor_sync(0xffffffffu, s, off);
    if (lane == 0) {
        int n = row & (Nc - 1);
        float diag = __ldg(adj + (size_t)row * Nc + n);
        float rs = s - diag + 1.0f;
        g_d[row] = 1.0f / (1e-6f + sqrtf(rs));
    }
}

// ---------------------------------------------------------------------------
// Kernel 2: z[r,o] = d[r] * sum_f x[r,f] W[f,o].
// Writes z (exact fp32, row-major) and zT (tf32-rounded, transposed).
// ---------------------------------------------------------------------------
__global__ __launch_bounds__(256) void k_xw(const float* __restrict__ x,
                                            const float* __restrict__ W) {
    __shared__ float As[8][132];
    __shared__ float Bs[8][128];
    int tid = threadIdx.x;
    int tx = tid & 15, ty = tid >> 4;
    int rowBase = blockIdx.x * 128;

    float c[8][8] = {};

    int aIdx = tid * 4;
    int aR = aIdx >> 3, aK = aIdx & 7;
    int bK = tid >> 5, bC = (tid & 31) * 4;

    for (int k0 = 0; k0 < Fc; k0 += 8) {
        float4 va = *reinterpret_cast<const float4*>(
            x + (size_t)(rowBase + aR) * Fc + k0 + aK);
        float4 vb = *reinterpret_cast<const float4*>(
            W + (size_t)(bK + k0) * Oc + bC);
        __syncthreads();
        As[aK + 0][aR] = va.x; As[aK + 1][aR] = va.y;
        As[aK + 2][aR] = va.z; As[aK + 3][aR] = va.w;
        *reinterpret_cast<float4*>(&Bs[bK][bC]) = vb;
        __syncthreads();
#pragma unroll
        for (int k = 0; k < 8; ++k) {
            float a[8], b[8];
#pragma unroll
            for (int i = 0; i < 8; i++) a[i] = As[k][ty * 8 + i];
#pragma unroll
            for (int j = 0; j < 8; j++) b[j] = Bs[k][tx * 8 + j];
#pragma unroll
            for (int i = 0; i < 8; i++)
#pragma unroll
                for (int j = 0; j < 8; j++) c[i][j] += a[i] * b[j];
        }
    }

    float dvv[8];
#pragma unroll
    for (int i = 0; i < 8; i++) dvv[i] = g_d[rowBase + ty * 8 + i];

    // exact row-major z (used in k_main epilogue correction)
#pragma unroll
    for (int i = 0; i < 8; i++) {
        int row = rowBase + ty * 8 + i;
#pragma unroll
        for (int j = 0; j < 8; j += 4) {
            float4 v;
            v.x = dvv[i] * c[i][j + 0];
            v.y = dvv[i] * c[i][j + 1];
            v.z = dvv[i] * c[i][j + 2];
            v.w = dvv[i] * c[i][j + 3];
            *reinterpret_cast<float4*>(g_z + (size_t)row * Oc + tx * 8 + j) = v;
        }
    }
    // transposed zT[b][o][m], pre-rounded to tf32 (RNA) so k_main needs no cvt
    int bb = rowBase >> 11;
    int mbase = (rowBase & (Nc - 1)) + ty * 8;
#pragma unroll
    for (int j = 0; j < 8; j++) {
        int o = tx * 8 + j;
        float* dst = g_zT + ((size_t)bb * Oc + o) * Nc + mbase;
        uint32_t u[8];
#pragma unroll
        for (int i = 0; i < 8; i++) {
            u[i] = __float_as_uint(dvv[i] * c[i][j]);
            TO_TF32(u[i]);
        }
        float4 v0, v1;
        v0.x = __uint_as_float(u[0]); v0.y = __uint_as_float(u[1]);
        v0.z = __uint_as_float(u[2]); v0.w = __uint_as_float(u[3]);
        v1.x = __uint_as_float(u[4]); v1.y = __uint_as_float(u[5]);
        v1.z = __uint_as_float(u[6]); v1.w = __uint_as_float(u[7]);
        *reinterpret_cast<float4*>(dst)     = v0;
        *reinterpret_cast<float4*>(dst + 4) = v1;
    }
}

// ---------------------------------------------------------------------------
// Kernel 3: tf32 mma.sync GEMM, 512 threads / 16 warps, zero cvt inner loop.
// out[b,n,o] = relu( d[n] * ( sum_m A[b,n,m] z[b,m,o] + (1-A[b,n,n]) z[b,n,o] ) )
// BM=128, BN=128, BK=32, 4-stage cp.async (128 KB smem).
// Warp tile 32x32: warpM = wid&3, warpN = wid>>2; 2x4 m16n8k8 tiles.
// A fed as raw fp32 bits (HW truncates to tf32); B pre-rounded in k_xw.
// ---------------------------------------------------------------------------
constexpr int BK      = 32;
constexpr int K_ITERS = Nc / BK;              // 64
constexpr int TILE_B  = 128 * BK * 4;         // 16384 per operand
constexpr int STAGE_B = 2 * TILE_B;           // 32768 (A + B)
constexpr int SMEM_SZ = 4 * STAGE_B;          // 131072
constexpr int THREADS = 512;

__device__ __forceinline__ uint32_t sw(int r, int ch) {   // ch in 0..7 (16B units)
    return (uint32_t)(r * 128) + (uint32_t)(((ch ^ (r & 7)) << 4));
}
__device__ __forceinline__ uint32_t ldsm_addr(uint32_t base, int rowBase,
                                              int chunkBase, int lane) {
    int row = rowBase + (lane & 7) + (((lane >> 3) & 1) << 3);
    int ch  = chunkBase + (lane >> 4);
    return base + sw(row, ch);
}

__global__ __launch_bounds__(THREADS, 1) void k_main_mma(const float* __restrict__ adj,
                                                         float* __restrict__ out) {
    extern __shared__ __align__(1024) char smem[];
    uint32_t sb = smem_u32(smem);
    int tid = threadIdx.x, wid = tid >> 5, lane = tid & 31;
    int b = blockIdx.y, rowBase = blockIdx.x * 128;
    int warpM = wid & 3, warpN = wid >> 2;

    const float* A  = adj  + (size_t)b * Nc * Nc;
    const float* ZT = g_zT + (size_t)b * Oc * Nc;

    float c[2][4][4] = {};

    auto issue = [&](int it) {
        int s = it & 3;
        uint32_t baseA = sb + s * STAGE_B;
        uint32_t baseB = baseA + TILE_B;
        int k0 = it * BK;
#pragma unroll
        for (int t = 0; t < 2; t++) {          // 1024 16B chunks / 512 thr
            int idx = tid + t * THREADS;
            int r = idx >> 3, ch = idx & 7;
            uint32_t so = sw(r, ch);
            cp16(baseA + so, A  + (size_t)(rowBase + r) * Nc + k0 + ch * 4);
            cp16(baseB + so, ZT + (size_t)r * Nc + k0 + ch * 4);
        }
        CP_COMMIT();
    };

    issue(0); issue(1); issue(2);

    for (int it = 0; it < K_ITERS; ++it) {
        if (it + 3 < K_ITERS) { issue(it + 3); CP_WAIT(3); }
        else                  { CP_WAIT(0); }
        __syncthreads();

        int s = it & 3;
        uint32_t baseA = sb + s * STAGE_B;
        uint32_t baseB = baseA + TILE_B;
#pragma unroll
        for (int ks = 0; ks < 4; ++ks) {       // four k8 steps within BK=32
            uint32_t a[2][4];
#pragma unroll
            for (int mt = 0; mt < 2; ++mt) {
                uint32_t ad = ldsm_addr(baseA, warpM * 32 + mt * 16, ks * 2, lane);
                LDSM4(a[mt], ad);              // raw fp32 bits; HMMA truncates
            }
            uint32_t bf[4][2];
#pragma unroll
            for (int p = 0; p < 2; ++p) {      // two n16 groups -> four n8 tiles
                uint32_t r4[4];
                uint32_t ad = ldsm_addr(baseB, warpN * 32 + p * 16, ks * 2, lane);
                LDSM4(r4, ad);                 // pre-rounded tf32, no cvt
                bf[2 * p + 0][0] = r4[0]; bf[2 * p + 0][1] = r4[2];
                bf[2 * p + 1][0] = r4[1]; bf[2 * p + 1][1] = r4[3];
            }
#pragma unroll
            for (int mt = 0; mt < 2; ++mt)
#pragma unroll
                for (int nt = 0; nt < 4; ++nt)
                    MMA_TF32(c[mt][nt], a[mt], bf[nt]);
        }
        __syncthreads();
    }

    // Epilogue: diagonal correction + d[n] scale + relu.
    int gr = lane >> 2, tg = lane & 3;
#pragma unroll
    for (int mt = 0; mt < 2; ++mt) {
        int n0 = rowBase + warpM * 32 + mt * 16 + gr;
        int n1 = n0 + 8;
        size_t rg0 = (size_t)b * Nc + n0;
        size_t rg1 = (size_t)b * Nc + n1;
        float corr0 = 1.0f - __ldg(A + (size_t)n0 * Nc + n0);
        float corr1 = 1.0f - __ldg(A + (size_t)n1 * Nc + n1);
        float dv0 = g_d[rg0], dv1 = g_d[rg1];
#pragma unroll
        for (int nt = 0; nt < 4; ++nt) {
            int o = warpN * 32 + nt * 8 + 2 * tg;
            float2 z0 = *reinterpret_cast<const float2*>(g_z + rg0 * Oc + o);
            float2 z1 = *reinterpret_cast<const float2*>(g_z + rg1 * Oc + o);
            float2 v0, v1;
            v0.x = fmaxf(dv0 * (c[mt][nt][0] + corr0 * z0.x), 0.f);
            v0.y = fmaxf(dv0 * (c[mt][nt][1] + corr0 * z0.y), 0.f);
            v1.x = fmaxf(dv1 * (c[mt][nt][2] + corr1 * z1.x), 0.f);
            v1.y = fmaxf(dv1 * (c[mt][nt][3] + corr1 * z1.y), 0.f);
            *reinterpret_cast<float2*>(out + rg0 * Oc + o) = v0;
            *reinterpret_cast<float2*>(out + rg1 * Oc + o) = v1;
        }
    }
}

// ---------------------------------------------------------------------------
extern "C" void kernel_launch(void* const* d_in, const int* in_sizes, int n_in,
                              void* d_out, int out_size) {
    const float* x   = (const float*)d_in[0];   // [8,2048,128]
    const float* adj = (const float*)d_in[1];   // [8,2048,2048]
    const float* W   = (const float*)d_in[2];   // [128,128]
    float* out = (float*)d_out;                 // [8,2048,128]

    cudaFuncSetAttribute(k_main_mma, cudaFuncAttributeMaxDynamicSharedMemorySize,
                         SMEM_SZ);

    k_rowsum<<<(Bc * Nc) / 8, 256>>>(adj);
    k_xw<<<(Bc * Nc) / 128, 256>>>(x, W);
    k_main_mma<<<dim3(Nc / 128, Bc), THREADS, SMEM_SZ>>>(adj, out);
}

// round 15
// speedup vs baseline: 1.0590x; 1.0011x over previous
#include <cuda_runtime.h>
#include <math.h>
#include <stdint.h>

// Problem shape (fixed by setup_inputs)
constexpr int Bc = 8;     // batch
constexpr int Nc = 2048;  // nodes
constexpr int Fc = 128;   // in features
constexpr int Oc = 128;   // out features

// Scratch (static __device__ — allocation-free per harness rules)
__device__ float g_d[Bc * Nc];            // 1/(eps+sqrt(rowsum(A_hat)))
__device__ float g_z[Bc * Nc * Oc];       // z[m,o] = d[m]*(xW)[m,o] exact fp32 (epilogue)
__device__ float g_zT[Bc * Oc * Nc];      // zT[o,m] = same, PRE-ROUNDED to tf32 (MMA B)

// ---------------------------------------------------------------------------
// Generic-PTX helpers (sm_80+ features only: cp.async, ldmatrix, mma.sync tf32)
// ---------------------------------------------------------------------------
__device__ __forceinline__ uint32_t smem_u32(const void* p) {
    uint32_t a;
    asm("{ .reg .u64 t; cvta.to.shared.u64 t, %1; cvt.u32.u64 %0, t; }"
        : "=r"(a) : "l"(p));
    return a;
}
__device__ __forceinline__ void cp16(uint32_t s, const void* g) {
    asm volatile("cp.async.cg.shared.global [%0], [%1], 16;\n" :: "r"(s), "l"(g));
}
#define CP_COMMIT()  asm volatile("cp.async.commit_group;\n" ::: "memory")
#define CP_WAIT(N)   asm volatile("cp.async.wait_group " #N ";\n" ::: "memory")

#define LDSM4(r, addr) \
    asm volatile("ldmatrix.sync.aligned.m8n8.x4.shared.b16 {%0,%1,%2,%3}, [%4];" \
                 : "=r"((r)[0]), "=r"((r)[1]), "=r"((r)[2]), "=r"((r)[3]) \
                 : "r"(addr))

#define TO_TF32(x) asm volatile("cvt.rna.tf32.f32 %0, %0;" : "+r"(x))

#define MMA_TF32(c, a, bb) \
    asm volatile( \
        "mma.sync.aligned.m16n8k8.row.col.f32.tf32.tf32.f32 " \
        "{%0,%1,%2,%3}, {%4,%5,%6,%7}, {%8,%9}, {%0,%1,%2,%3};" \
        : "+f"((c)[0]), "+f"((c)[1]), "+f"((c)[2]), "+f"((c)[3]) \
        : "r"((a)[0]), "r"((a)[1]), "r"((a)[2]), "r"((a)[3]), \
          "r"((bb)[0]), "r"((bb)[1]))

// ---------------------------------------------------------------------------
// Kernel 1: row sums of A_hat -> d.  One warp per row, deeper MLP.
// ---------------------------------------------------------------------------
__global__ __launch_bounds__(256) void k_rowsum(const float* __restrict__ adj) {
    int row = blockIdx.x * 8 + (threadIdx.x >> 5);
    if (row >= Bc * Nc) return;
    int lane = threadIdx.x & 31;
    const float4* a = reinterpret_cast<const float4*>(adj + (size_t)row * Nc);
    float s0 = 0.f, s1 = 0.f;
    // 512 float4 per row / 32 lanes = 16 iters; unroll fully in pairs -> MLP 16
#pragma unroll 8
    for (int i = lane; i < Nc / 4; i += 64) {
        float4 v0 = __ldg(a + i);
        float4 v1 = __ldg(a + i + 32);
        s0 += (v0.x + v0.y) + (v0.z + v0.w);
        s1 += (v1.x + v1.y) + (v1.z + v1.w);
    }
    float s = s0 + s1;
#pragma unroll
    for (int off = 16; off; off >>= 1) s += __shfl_xor_sync(0xffffffffu, s, off);
    if (lane == 0) {
        int n = row & (Nc - 1);
        float diag = __ldg(adj + (size_t)row * Nc + n);
        float rs = s - diag + 1.0f;
        g_d[row] = 1.0f / (1e-6f + sqrtf(rs));
    }
}

// ---------------------------------------------------------------------------
// Kernel 2: z[r,o] = d[r] * sum_f x[r,f] W[f,o].
// Writes z (exact fp32, row-major) and zT (tf32-rounded, transposed).
// ---------------------------------------------------------------------------
__global__ __launch_bounds__(256) void k_xw(const float* __restrict__ x,
                                            const float* __restrict__ W) {
    __shared__ float As[8][132];
    __shared__ float Bs[8][128];
    int tid = threadIdx.x;
    int tx = tid & 15, ty = tid >> 4;
    int rowBase = blockIdx.x * 128;

    float c[8][8] = {};

    int aIdx = tid * 4;
    int aR = aIdx >> 3, aK = aIdx & 7;
    int bK = tid >> 5, bC = (tid & 31) * 4;

    for (int k0 = 0; k0 < Fc; k0 += 8) {
        float4 va = *reinterpret_cast<const float4*>(
            x + (size_t)(rowBase + aR) * Fc + k0 + aK);
        float4 vb = *reinterpret_cast<const float4*>(
            W + (size_t)(bK + k0) * Oc + bC);
        __syncthreads();
        As[aK + 0][aR] = va.x; As[aK + 1][aR] = va.y;
        As[aK + 2][aR] = va.z; As[aK + 3][aR] = va.w;
        *reinterpret_cast<float4*>(&Bs[bK][bC]) = vb;
        __syncthreads();
#pragma unroll
        for (int k = 0; k < 8; ++k) {
            float a[8], b[8];
#pragma unroll
            for (int i = 0; i < 8; i++) a[i] = As[k][ty * 8 + i];
#pragma unroll
            for (int j = 0; j < 8; j++) b[j] = Bs[k][tx * 8 + j];
#pragma unroll
            for (int i = 0; i < 8; i++)
#pragma unroll
                for (int j = 0; j < 8; j++) c[i][j] += a[i] * b[j];
        }
    }

    float dvv[8];
#pragma unroll
    for (int i = 0; i < 8; i++) dvv[i] = g_d[rowBase + ty * 8 + i];

    // exact row-major z (used in k_main epilogue correction)
#pragma unroll
    for (int i = 0; i < 8; i++) {
        int row = rowBase + ty * 8 + i;
#pragma unroll
        for (int j = 0; j < 8; j += 4) {
            float4 v;
            v.x = dvv[i] * c[i][j + 0];
            v.y = dvv[i] * c[i][j + 1];
            v.z = dvv[i] * c[i][j + 2];
            v.w = dvv[i] * c[i][j + 3];
            *reinterpret_cast<float4*>(g_z + (size_t)row * Oc + tx * 8 + j) = v;
        }
    }
    // transposed zT[b][o][m], pre-rounded to tf32 (RNA) so k_main needs no cvt
    int bb = rowBase >> 11;
    int mbase = (rowBase & (Nc - 1)) + ty * 8;
#pragma unroll
    for (int j = 0; j < 8; j++) {
        int o = tx * 8 + j;
        float* dst = g_zT + ((size_t)bb * Oc + o) * Nc + mbase;
        uint32_t u[8];
#pragma unroll
        for (int i = 0; i < 8; i++) {
            u[i] = __float_as_uint(dvv[i] * c[i][j]);
            TO_TF32(u[i]);
        }
        float4 v0, v1;
        v0.x = __uint_as_float(u[0]); v0.y = __uint_as_float(u[1]);
        v0.z = __uint_as_float(u[2]); v0.w = __uint_as_float(u[3]);
        v1.x = __uint_as_float(u[4]); v1.y = __uint_as_float(u[5]);
        v1.z = __uint_as_float(u[6]); v1.w = __uint_as_float(u[7]);
        *reinterpret_cast<float4*>(dst)     = v0;
        *reinterpret_cast<float4*>(dst + 4) = v1;
    }
}

// ---------------------------------------------------------------------------
// Kernel 3: tf32 mma.sync GEMM, 512 threads / 16 warps, zero cvt inner loop.
// out[b,n,o] = relu( d[n] * ( sum_m A[b,n,m] z[b,m,o] + (1-A[b,n,n]) z[b,n,o] ) )
// BM=128, BN=128, BK=32, 4-stage cp.async (128 KB smem).
// Warp tile 32x32: warpM = wid&3, warpN = wid>>2; 2x4 m16n8k8 tiles.
// A fed as raw fp32 bits (HW truncates to tf32); B pre-rounded in k_xw.
// ---------------------------------------------------------------------------
constexpr int BK      = 32;
constexpr int K_ITERS = Nc / BK;              // 64
constexpr int TILE_B  = 128 * BK * 4;         // 16384 per operand
constexpr int STAGE_B = 2 * TILE_B;           // 32768 (A + B)
constexpr int SMEM_SZ = 4 * STAGE_B;          // 131072
constexpr int THREADS = 512;

__device__ __forceinline__ uint32_t sw(int r, int ch) {   // ch in 0..7 (16B units)
    return (uint32_t)(r * 128) + (uint32_t)(((ch ^ (r & 7)) << 4));
}
__device__ __forceinline__ uint32_t ldsm_addr(uint32_t base, int rowBase,
                                              int chunkBase, int lane) {
    int row = rowBase + (lane & 7) + (((lane >> 3) & 1) << 3);
    int ch  = chunkBase + (lane >> 4);
    return base + sw(row, ch);
}

__global__ __launch_bounds__(THREADS, 1) void k_main_mma(const float* __restrict__ adj,
                                                         float* __restrict__ out) {
    extern __shared__ __align__(1024) char smem[];
    uint32_t sb = smem_u32(smem);
    int tid = threadIdx.x, wid = tid >> 5, lane = tid & 31;
    int b = blockIdx.y, rowBase = blockIdx.x * 128;
    int warpM = wid & 3, warpN = wid >> 2;

    const float* A  = adj  + (size_t)b * Nc * Nc;
    const float* ZT = g_zT + (size_t)b * Oc * Nc;

    float c[2][4][4] = {};

    auto issue = [&](int it) {
        int s = it & 3;
        uint32_t baseA = sb + s * STAGE_B;
        uint32_t baseB = baseA + TILE_B;
        int k0 = it * BK;
#pragma unroll
        for (int t = 0; t < 2; t++) {          // 1024 16B chunks / 512 thr
            int idx = tid + t * THREADS;
            int r = idx >> 3, ch = idx & 7;
            uint32_t so = sw(r, ch);
            cp16(baseA + so, A  + (size_t)(rowBase + r) * Nc + k0 + ch * 4);
            cp16(baseB + so, ZT + (size_t)r * Nc + k0 + ch * 4);
        }
        CP_COMMIT();
    };

    issue(0); issue(1); issue(2);

    for (int it = 0; it < K_ITERS; ++it) {
        if (it + 3 < K_ITERS) { issue(it + 3); CP_WAIT(3); }
        else                  { CP_WAIT(0); }
        __syncthreads();

        int s = it & 3;
        uint32_t baseA = sb + s * STAGE_B;
        uint32_t baseB = baseA + TILE_B;
#pragma unroll
        for (int ks = 0; ks < 4; ++ks) {       // four k8 steps within BK=32
            uint32_t a[2][4];
#pragma unroll
            for (int mt = 0; mt < 2; ++mt) {
                uint32_t ad = ldsm_addr(baseA, warpM * 32 + mt * 16, ks * 2, lane);
                LDSM4(a[mt], ad);              // raw fp32 bits; HMMA truncates
            }
            uint32_t bf[4][2];
#pragma unroll
            for (int p = 0; p < 2; ++p) {      // two n16 groups -> four n8 tiles
                uint32_t r4[4];
                uint32_t ad = ldsm_addr(baseB, warpN * 32 + p * 16, ks * 2, lane);
                LDSM4(r4, ad);                 // pre-rounded tf32, no cvt
                bf[2 * p + 0][0] = r4[0]; bf[2 * p + 0][1] = r4[2];
                bf[2 * p + 1][0] = r4[1]; bf[2 * p + 1][1] = r4[3];
            }
#pragma unroll
            for (int mt = 0; mt < 2; ++mt)
#pragma unroll
                for (int nt = 0; nt < 4; ++nt)
                    MMA_TF32(c[mt][nt], a[mt], bf[nt]);
        }
        __syncthreads();
    }

    // Epilogue: diagonal correction + d[n] scale + relu.
    int gr = lane >> 2, tg = lane & 3;
#pragma unroll
    for (int mt = 0; mt < 2; ++mt) {
        int n0 = rowBase + warpM * 32 + mt * 16 + gr;
        int n1 = n0 + 8;
        size_t rg0 = (size_t)b * Nc + n0;
        size_t rg1 = (size_t)b * Nc + n1;
        float corr0 = 1.0f - __ldg(A + (size_t)n0 * Nc + n0);
        float corr1 = 1.0f - __ldg(A + (size_t)n1 * Nc + n1);
        float dv0 = g_d[rg0], dv1 = g_d[rg1];
#pragma unroll
        for (int nt = 0; nt < 4; ++nt) {
            int o = warpN * 32 + nt * 8 + 2 * tg;
            float2 z0 = *reinterpret_cast<const float2*>(g_z + rg0 * Oc + o);
            float2 z1 = *reinterpret_cast<const float2*>(g_z + rg1 * Oc + o);
            float2 v0, v1;
            v0.x = fmaxf(dv0 * (c[mt][nt][0] + corr0 * z0.x), 0.f);
            v0.y = fmaxf(dv0 * (c[mt][nt][1] + corr0 * z0.y), 0.f);
            v1.x = fmaxf(dv1 * (c[mt][nt][2] + corr1 * z1.x), 0.f);
            v1.y = fmaxf(dv1 * (c[mt][nt][3] + corr1 * z1.y), 0.f);
            *reinterpret_cast<float2*>(out + rg0 * Oc + o) = v0;
            *reinterpret_cast<float2*>(out + rg1 * Oc + o) = v1;
        }
    }
}

// ---------------------------------------------------------------------------
extern "C" void kernel_launch(void* const* d_in, const int* in_sizes, int n_in,
                              void* d_out, int out_size) {
    const float* x   = (const float*)d_in[0];   // [8,2048,128]
    const float* adj = (const float*)d_in[1];   // [8,2048,2048]
    const float* W   = (const float*)d_in[2];   // [128,128]
    float* out = (float*)d_out;                 // [8,2048,128]

    cudaFuncSetAttribute(k_main_mma, cudaFuncAttributeMaxDynamicSharedMemorySize,
                         SMEM_SZ);

    k_rowsum<<<(Bc * Nc) / 8, 256>>>(adj);
    k_xw<<<(Bc * Nc) / 128, 256>>>(x, W);
    k_main_mma<<<dim3(Nc / 128, Bc), THREADS, SMEM_SZ>>>(adj, out);
}

// round 16
// speedup vs baseline: 1.1363x; 1.0730x over previous
#include <cuda_runtime.h>
#include <math.h>
#include <stdint.h>

// Problem shape (fixed by setup_inputs)
constexpr int Bc = 8;     // batch
constexpr int Nc = 2048;  // nodes
constexpr int Fc = 128;   // in features
constexpr int Oc = 128;   // out features

// Scratch (static __device__ — allocation-free per harness rules)
__device__ float g_d[Bc * Nc];            // 1/(eps+sqrt(rowsum(A_hat)))
__device__ float g_z[Bc * Nc * Oc];       // z[m,o] = d[m]*(xW)[m,o] exact fp32
__device__ float g_zT[Bc * Oc * Nc];      // zT[o,m] pre-rounded tf32 (MMA B operand)

// ---------------------------------------------------------------------------
// Generic-PTX helpers (sm_80+ features only: cp.async, ldmatrix, mma.sync tf32)
// ---------------------------------------------------------------------------
__device__ __forceinline__ uint32_t smem_u32(const void* p) {
    uint32_t a;
    asm("{ .reg .u64 t; cvta.to.shared.u64 t, %1; cvt.u32.u64 %0, t; }"
        : "=r"(a) : "l"(p));
    return a;
}
__device__ __forceinline__ void cp16(uint32_t s, const void* g) {
    asm volatile("cp.async.cg.shared.global [%0], [%1], 16;\n" :: "r"(s), "l"(g));
}
#define CP_COMMIT()  asm volatile("cp.async.commit_group;\n" ::: "memory")
#define CP_WAIT(N)   asm volatile("cp.async.wait_group " #N ";\n" ::: "memory")

#define LDSM4(r, addr) \
    asm volatile("ldmatrix.sync.aligned.m8n8.x4.shared.b16 {%0,%1,%2,%3}, [%4];" \
                 : "=r"((r)[0]), "=r"((r)[1]), "=r"((r)[2]), "=r"((r)[3]) \
                 : "r"(addr))

#define TO_TF32(x) asm volatile("cvt.rna.tf32.f32 %0, %0;" : "+r"(x))

#define MMA_TF32(c, a, bb) \
    asm volatile( \
        "mma.sync.aligned.m16n8k8.row.col.f32.tf32.tf32.f32 " \
        "{%0,%1,%2,%3}, {%4,%5,%6,%7}, {%8,%9}, {%0,%1,%2,%3};" \
        : "+f"((c)[0]), "+f"((c)[1]), "+f"((c)[2]), "+f"((c)[3]) \
        : "r"((a)[0]), "r"((a)[1]), "r"((a)[2]), "r"((a)[3]), \
          "r"((bb)[0]), "r"((bb)[1]))

// ---------------------------------------------------------------------------
// Kernel 1 (fused): per CTA (128 rows):
//   - rowsum of adj rows -> d          (DRAM-bound, LDGs hidden under FFMA)
//   - z' = x W                         (FFMA SGEMM, exact fp32)
//   - epilogue: z = d*z' (fp32, row-major) and zT = tf32(d*z') (transposed)
// Warp w sums one adj row per k-iter (16 iters x 8 warps = 128 rows).
// Row loads are issued into registers BEFORE the FFMA block and consumed after,
// so the ~600-cycle DRAM latency overlaps the 512-FFMA compute block.
// ---------------------------------------------------------------------------
__global__ __launch_bounds__(256, 1) void k_pre(const float* __restrict__ x,
                                                const float* __restrict__ W,
                                                const float* __restrict__ adj) {
    __shared__ float As[8][132];
    __shared__ float Bs[8][128];
    __shared__ float sd[128];
    int tid = threadIdx.x;
    int tx = tid & 15, ty = tid >> 4;
    int wid = tid >> 5, lane = tid & 31;
    int rowBase = blockIdx.x * 128;

    float c[8][8] = {};

    int aIdx = tid * 4;
    int aR = aIdx >> 3, aK = aIdx & 7;
    int bK = tid >> 5, bC = (tid & 31) * 4;

    for (int kk = 0; kk < 16; ++kk) {
        int k0 = kk * 8;
        float4 va = *reinterpret_cast<const float4*>(
            x + (size_t)(rowBase + aR) * Fc + k0 + aK);
        float4 vb = *reinterpret_cast<const float4*>(
            W + (size_t)(bK + k0) * Oc + bC);

        // issue this warp's adj-row loads (row = wid*16 + kk), consume later
        int lr = wid * 16 + kk;
        const float4* ar = reinterpret_cast<const float4*>(
            adj + (size_t)(rowBase + lr) * Nc);
        float4 rv[16];
#pragma unroll
        for (int i = 0; i < 16; i++) rv[i] = __ldg(ar + lane + i * 32);

        __syncthreads();
        As[aK + 0][aR] = va.x; As[aK + 1][aR] = va.y;
        As[aK + 2][aR] = va.z; As[aK + 3][aR] = va.w;
        *reinterpret_cast<float4*>(&Bs[bK][bC]) = vb;
        __syncthreads();
#pragma unroll
        for (int k = 0; k < 8; ++k) {
            float a[8], b[8];
#pragma unroll
            for (int i = 0; i < 8; i++) a[i] = As[k][ty * 8 + i];
#pragma unroll
            for (int j = 0; j < 8; j++) b[j] = Bs[k][tx * 8 + j];
#pragma unroll
            for (int i = 0; i < 8; i++)
#pragma unroll
                for (int j = 0; j < 8; j++) c[i][j] += a[i] * b[j];
        }
        // consume row loads (landed during FFMA block), reduce, emit d
        float s = 0.f;
#pragma unroll
        for (int i = 0; i < 16; i++)
            s += (rv[i].x + rv[i].y) + (rv[i].z + rv[i].w);
#pragma unroll
        for (int off = 16; off; off >>= 1)
            s += __shfl_xor_sync(0xffffffffu, s, off);
        if (lane == 0) {
            int gr_ = rowBase + lr;
            float diag = __ldg(adj + (size_t)gr_ * Nc + (gr_ & (Nc - 1)));
            float dv = 1.0f / (1e-6f + sqrtf(s - diag + 1.0f));
            sd[lr] = dv;
            g_d[gr_] = dv;
        }
    }
    __syncthreads();

    float dvv[8];
#pragma unroll
    for (int i = 0; i < 8; i++) dvv[i] = sd[ty * 8 + i];

    // exact row-major z (used in k_main epilogue correction)
#pragma unroll
    for (int i = 0; i < 8; i++) {
        int row = rowBase + ty * 8 + i;
#pragma unroll
        for (int j = 0; j < 8; j += 4) {
            float4 v;
            v.x = dvv[i] * c[i][j + 0];
            v.y = dvv[i] * c[i][j + 1];
            v.z = dvv[i] * c[i][j + 2];
            v.w = dvv[i] * c[i][j + 3];
            *reinterpret_cast<float4*>(g_z + (size_t)row * Oc + tx * 8 + j) = v;
        }
    }
    // transposed zT[b][o][m], pre-rounded to tf32 (RNA) so k_main needs no cvt
    int bb = rowBase >> 11;
    int mbase = (rowBase & (Nc - 1)) + ty * 8;
#pragma unroll
    for (int j = 0; j < 8; j++) {
        int o = tx * 8 + j;
        float* dst = g_zT + ((size_t)bb * Oc + o) * Nc + mbase;
        uint32_t u[8];
#pragma unroll
        for (int i = 0; i < 8; i++) {
            u[i] = __float_as_uint(dvv[i] * c[i][j]);
            TO_TF32(u[i]);
        }
        float4 v0, v1;
        v0.x = __uint_as_float(u[0]); v0.y = __uint_as_float(u[1]);
        v0.z = __uint_as_float(u[2]); v0.w = __uint_as_float(u[3]);
        v1.x = __uint_as_float(u[4]); v1.y = __uint_as_float(u[5]);
        v1.z = __uint_as_float(u[6]); v1.w = __uint_as_float(u[7]);
        *reinterpret_cast<float4*>(dst)     = v0;
        *reinterpret_cast<float4*>(dst + 4) = v1;
    }
}

// ---------------------------------------------------------------------------
// Kernel 2: tf32 mma.sync GEMM.
// out[b,n,o] = relu( d[n] * ( sum_m A[b,n,m] z[b,m,o] + (1-A[b,n,n]) z[b,n,o] ) )
// BM=128, BN=128, BK=32. 8 warps, warp tile 32x64 (warpM=wid&3, warpN=wid>>2):
// LDSM traffic 96 KB/iter (A x2, B x4 redundancy) vs 128 KB at 4x4.
// 6-stage cp.async pipeline (192 KB smem), prefetch distance 4,
// ONE __syncthreads per iter (stage-reuse distance 5 > max warp skew 1).
// A fed as raw fp32 bits (HMMA truncates to tf32); B pre-rounded in k_pre.
// ---------------------------------------------------------------------------
constexpr int BK      = 32;
constexpr int K_ITERS = Nc / BK;              // 64
constexpr int TILE_B  = 128 * BK * 4;         // 16384 per operand
constexpr int STAGE_B = 2 * TILE_B;           // 32768 (A + B)
constexpr int STAGES  = 6;
constexpr int SMEM_SZ = STAGES * STAGE_B;     // 196608
constexpr int THREADS = 256;

__device__ __forceinline__ uint32_t sw(int r, int ch) {   // ch in 0..7 (16B units)
    return (uint32_t)(r * 128) + (uint32_t)(((ch ^ (r & 7)) << 4));
}
__device__ __forceinline__ uint32_t ldsm_addr(uint32_t base, int rowBase,
                                              int chunkBase, int lane) {
    int row = rowBase + (lane & 7) + (((lane >> 3) & 1) << 3);
    int ch  = chunkBase + (lane >> 4);
    return base + sw(row, ch);
}

__global__ __launch_bounds__(THREADS, 1) void k_main_mma(const float* __restrict__ adj,
                                                         float* __restrict__ out) {
    extern __shared__ __align__(1024) char smem[];
    uint32_t sb = smem_u32(smem);
    int tid = threadIdx.x, wid = tid >> 5, lane = tid & 31;
    int b = blockIdx.y, rowBase = blockIdx.x * 128;
    int warpM = wid & 3, warpN = wid >> 2;     // 4 x 2 -> warp tile 32 x 64

    const float* A  = adj  + (size_t)b * Nc * Nc;
    const float* ZT = g_zT + (size_t)b * Oc * Nc;

    float c[2][8][4] = {};

    auto issue = [&](int it) {
        int s = it % STAGES;
        uint32_t baseA = sb + s * STAGE_B;
        uint32_t baseB = baseA + TILE_B;
        int k0 = it * BK;
#pragma unroll
        for (int t = 0; t < 4; t++) {          // 1024 chunks/operand / 256 thr
            int idx = tid + t * THREADS;
            int r = idx >> 3, ch = idx & 7;
            uint32_t so = sw(r, ch);
            cp16(baseA + so, A  + (size_t)(rowBase + r) * Nc + k0 + ch * 4);
            cp16(baseB + so, ZT + (size_t)r * Nc + k0 + ch * 4);
        }
        CP_COMMIT();
    };

    issue(0); issue(1); issue(2); issue(3);

    for (int it = 0; it < K_ITERS; ++it) {
        if (it + 4 < K_ITERS) { issue(it + 4); CP_WAIT(4); }
        else                  { CP_WAIT(0); }
        __syncthreads();                       // single barrier per iter

        int s = it % STAGES;
        uint32_t baseA = sb + s * STAGE_B;
        uint32_t baseB = baseA + TILE_B;
#pragma unroll
        for (int ks = 0; ks < 4; ++ks) {       // four k8 steps within BK=32
            uint32_t a[2][4];
#pragma unroll
            for (int mt = 0; mt < 2; ++mt) {
                uint32_t ad = ldsm_addr(baseA, warpM * 32 + mt * 16, ks * 2, lane);
                LDSM4(a[mt], ad);              // raw fp32 bits; HMMA truncates
            }
            uint32_t bf[8][2];
#pragma unroll
            for (int p = 0; p < 4; ++p) {      // four n16 groups -> eight n8 tiles
                uint32_t r4[4];
                uint32_t ad = ldsm_addr(baseB, warpN * 64 + p * 16, ks * 2, lane);
                LDSM4(r4, ad);                 // pre-rounded tf32, no cvt
                bf[2 * p + 0][0] = r4[0]; bf[2 * p + 0][1] = r4[2];
                bf[2 * p + 1][0] = r4[1]; bf[2 * p + 1][1] = r4[3];
            }
#pragma unroll
            for (int mt = 0; mt < 2; ++mt)
#pragma unroll
                for (int nt = 0; nt < 8; ++nt)
                    MMA_TF32(c[mt][nt], a[mt], bf[nt]);
        }
        // no trailing barrier: next write targets stage (it+5)%6, the slowest
        // reader is at stage (it)%6 at worst (skew bounded by the barrier above)
    }

    // Epilogue: diagonal correction + d[n] scale + relu.
    int gr = lane >> 2, tg = lane & 3;
#pragma unroll
    for (int mt = 0; mt < 2; ++mt) {
        int n0 = rowBase + warpM * 32 + mt * 16 + gr;
        int n1 = n0 + 8;
        size_t rg0 = (size_t)b * Nc + n0;
        size_t rg1 = (size_t)b * Nc + n1;
        float corr0 = 1.0f - __ldg(A + (size_t)n0 * Nc + n0);
        float corr1 = 1.0f - __ldg(A + (size_t)n1 * Nc + n1);
        float dv0 = g_d[rg0], dv1 = g_d[rg1];
#pragma unroll
        for (int nt = 0; nt < 8; ++nt) {
            int o = warpN * 64 + nt * 8 + 2 * tg;
            float2 z0 = *reinterpret_cast<const float2*>(g_z + rg0 * Oc + o);
            float2 z1 = *reinterpret_cast<const float2*>(g_z + rg1 * Oc + o);
            float2 v0, v1;
            v0.x = fmaxf(dv0 * (c[mt][nt][0] + corr0 * z0.x), 0.f);
            v0.y = fmaxf(dv0 * (c[mt][nt][1] + corr0 * z0.y), 0.f);
            v1.x = fmaxf(dv1 * (c[mt][nt][2] + corr1 * z1.x), 0.f);
            v1.y = fmaxf(dv1 * (c[mt][nt][3] + corr1 * z1.y), 0.f);
            *reinterpret_cast<float2*>(out + rg0 * Oc + o) = v0;
            *reinterpret_cast<float2*>(out + rg1 * Oc + o) = v1;
        }
    }
}

// ---------------------------------------------------------------------------
extern "C" void kernel_launch(void* const* d_in, const int* in_sizes, int n_in,
                              void* d_out, int out_size) {
    const float* x   = (const float*)d_in[0];   // [8,2048,128]
    const float* adj = (const float*)d_in[1];   // [8,2048,2048]
    const float* W   = (const float*)d_in[2];   // [128,128]
    float* out = (float*)d_out;                 // [8,2048,128]

    cudaFuncSetAttribute(k_main_mma, cudaFuncAttributeMaxDynamicSharedMemorySize,
                         SMEM_SZ);

    k_pre<<<(Bc * Nc) / 128, 256>>>(x, W, adj);
    k_main_mma<<<dim3(Nc / 128, Bc), THREADS, SMEM_SZ>>>(adj, out);
}